// round 11
// baseline (speedup 1.0000x reference)
#include <cuda_runtime.h>
#include <math.h>
#include <stdint.h>

// Problem constants
#define Bz 4
#define Cc 256
#define Oo 256
#define Gg 8
#define CG 32      // C/G
#define OG 32      // O/G
#define Hh 64
#define Ww 64
#define HW 4096
#define Nn 9
#define CO_OFF 144
#define CO_MASK 72
#define CO_ALL 216

// ---------------- scratch (device globals; no allocation allowed) ----------
__device__ float d_inp[(size_t)Bz * Gg * HW * CG];   // 16 MB  layout [b][g][p][c]
__device__ float d_x1[(size_t)Bz * Cc * HW];          // 16 MB  layout [b][c][p]
__device__ float d_offb[(size_t)Bz * CO_OFF * HW];    // 9 MB   layout [b][co][p]
__device__ float d_maskb[(size_t)Bz * CO_MASK * HW];  // 4.5 MB layout [b][co][p]
__device__ double d_stats[Bz * 2];

#define CP16(dst, src) \
    asm volatile("cp.async.cg.shared.global [%0], [%1], 16;" ::"r"(dst), "l"(src) : "memory")
#define CP_COMMIT() asm volatile("cp.async.commit_group;" ::: "memory")
#define CP_WAIT1() asm volatile("cp.async.wait_group 1;" ::: "memory")

// packed fp32x2 FMA (Blackwell FFMA2 — only reachable via PTX f32x2)
#define FMA2(acc, a, b) \
    asm("fma.rn.f32x2 %0, %1, %2, %0;" : "+l"(acc) : "l"(a), "l"(b))
#define PACKDUP(u, x) asm("mov.b64 %0, {%1,%1};" : "=l"(u) : "f"(x))
#define UNPK(x, y, u) asm("mov.b64 {%0,%1}, %2;" : "=f"(x), "=f"(y) : "l"(u))

// ---------------- K1: in_proj (1x1 conv) -> d_inp [b][g][p][c] ------------
// per batch GEMM: out[p][d] = sum_c x[b][c][p] * Wp[d][c]   (f32x2 packed)
__global__ __launch_bounds__(256) void k_inproj(const float* __restrict__ x,
                                                const float* __restrict__ Wp,
                                                const float* __restrict__ bp) {
    int b = blockIdx.z;
    int d0 = blockIdx.y * 64;
    int p0 = blockIdx.x * 64;
    __shared__ float Xs[16][64];
    __shared__ float Ws[16][66];  // even pitch -> 8B-aligned pairs
    int tid = threadIdx.x;
    int tx = tid & 15, ty = tid >> 4;
    unsigned long long acc2[4][2];
#pragma unroll
    for (int j = 0; j < 4; j++) {
        acc2[j][0] = 0ull;
        acc2[j][1] = 0ull;
    }
    const float* xb = x + (size_t)b * Cc * HW;
    for (int c0 = 0; c0 < Cc; c0 += 16) {
        for (int idx = tid; idx < 1024; idx += 256) {
            int k = idx >> 6, pp = idx & 63;
            Xs[k][pp] = xb[(size_t)(c0 + k) * HW + p0 + pp];
        }
        for (int idx = tid; idx < 1024; idx += 256) {
            int dd = idx >> 4, k = idx & 15;
            Ws[k][dd] = Wp[(size_t)(d0 + dd) * Cc + c0 + k];
        }
        __syncthreads();
#pragma unroll
        for (int k = 0; k < 16; k++) {
            unsigned long long b01 =
                *reinterpret_cast<const unsigned long long*>(&Ws[k][tx * 4]);
            unsigned long long b23 =
                *reinterpret_cast<const unsigned long long*>(&Ws[k][tx * 4 + 2]);
#pragma unroll
            for (int j = 0; j < 4; j++) {
                unsigned long long a2;
                PACKDUP(a2, Xs[k][ty * 4 + j]);
                FMA2(acc2[j][0], a2, b01);
                FMA2(acc2[j][1], a2, b23);
            }
        }
        __syncthreads();
    }
#pragma unroll
    for (int j = 0; j < 4; j++) {
        int p = p0 + ty * 4 + j;
        float r[4];
        UNPK(r[0], r[1], acc2[j][0]);
        UNPK(r[2], r[3], acc2[j][1]);
#pragma unroll
        for (int i = 0; i < 4; i++) {
            int d = d0 + tx * 4 + i;
            d_inp[(((size_t)b * Gg + (d >> 5)) * HW + p) * CG + (d & 31)] =
                r[i] + bp[d];
        }
    }
}

// ---------------- K2: depthwise 3x3 conv + partial LN sums ----------------
__global__ __launch_bounds__(256) void k_dwconv(const float* __restrict__ x,
                                                const float* __restrict__ dww,
                                                const float* __restrict__ dwb) {
    int bc = blockIdx.x;
    int b = bc >> 8, c = bc & 255;
    const float* xp = x + (size_t)(b * Cc + c) * HW;
    float* outp = d_x1 + (size_t)(b * Cc + c) * HW;
    float wr[9];
#pragma unroll
    for (int t = 0; t < 9; t++) wr[t] = dww[c * 9 + t];
    float bias = dwb[c];
    double s1 = 0.0, s2 = 0.0;
    int tid = threadIdx.x;
    for (int p = tid; p < HW; p += 256) {
        int h = p >> 6, w = p & 63;
        float acc = bias;
#pragma unroll
        for (int dy = 0; dy < 3; dy++) {
            int yy = h + dy - 1;
            if ((unsigned)yy < (unsigned)Hh) {
#pragma unroll
                for (int dx = 0; dx < 3; dx++) {
                    int xx = w + dx - 1;
                    if ((unsigned)xx < (unsigned)Ww)
                        acc += xp[yy * Ww + xx] * wr[dy * 3 + dx];
                }
            }
        }
        outp[p] = acc;
        s1 += (double)acc;
        s2 += (double)acc * (double)acc;
    }
    __shared__ double rs1[256];
    __shared__ double rs2[256];
    rs1[tid] = s1;
    rs2[tid] = s2;
    __syncthreads();
    for (int off = 128; off > 0; off >>= 1) {
        if (tid < off) {
            rs1[tid] += rs1[tid + off];
            rs2[tid] += rs2[tid + off];
        }
        __syncthreads();
    }
    if (tid == 0) {
        atomicAdd(&d_stats[b * 2 + 0], rs1[0]);
        atomicAdd(&d_stats[b * 2 + 1], rs2[0]);
    }
}

// ---------------- K4: LN (inline stats) + exact GELU, float4 --------------
__global__ __launch_bounds__(256) void k_lngelu() {
    __shared__ float s_mu, s_istd;
    size_t idx4 = (size_t)blockIdx.x * 256 + threadIdx.x;
    const size_t total4 = (size_t)Bz * Cc * HW / 4;
    int b = blockIdx.x >> 10;  // 1024 blocks per batch image
    if (threadIdx.x == 0) {
        const double Np = (double)Cc * HW;
        double mu = d_stats[b * 2 + 0] / Np;
        double var = d_stats[b * 2 + 1] / Np - mu * mu;
        s_mu = (float)mu;
        s_istd = (float)(1.0 / sqrt(var + 1e-5));
    }
    __syncthreads();
    if (idx4 >= total4) return;
    float mu = s_mu, istd = s_istd;
    float4 q = reinterpret_cast<float4*>(d_x1)[idx4];
    float v;
    v = (q.x - mu) * istd;
    q.x = 0.5f * v * (1.f + erff(v * 0.70710678118654752f));
    v = (q.y - mu) * istd;
    q.y = 0.5f * v * (1.f + erff(v * 0.70710678118654752f));
    v = (q.z - mu) * istd;
    q.z = 0.5f * v * (1.f + erff(v * 0.70710678118654752f));
    v = (q.w - mu) * istd;
    q.w = 0.5f * v * (1.f + erff(v * 0.70710678118654752f));
    reinterpret_cast<float4*>(d_x1)[idx4] = q;
}

// ---------------- K5: heads conv as implicit-GEMM tf32 mma.sync -----------
// (known-best 128-px config) cp.async double-buffered, 128 px x 112 co.
#define PATCH_F (2 * 8 * 4 * 72)     // 4608 floats
#define WS_F (2 * 112 * 76)          // 17024 floats
#define HEADS_SMEM ((PATCH_F + WS_F) * 4)  // 86528 bytes

__global__ __launch_bounds__(256) void k_heads_mma(const float* __restrict__ offw,
                                                   const float* __restrict__ offbias,
                                                   const float* __restrict__ maskw,
                                                   const float* __restrict__ maskbias) {
    extern __shared__ float dynsm[];
    float* patchp = dynsm;                 // [(buf*8+ci)*4+r]*72 + col
    float* wsp = dynsm + PATCH_F;          // [(buf*112+col)*76 + k]

    int b = blockIdx.z;
    int p0 = blockIdx.x * 128;
    int n0 = blockIdx.y * 112;
    int h0 = p0 >> 6;
    int tid = threadIdx.x;
    int warp = tid >> 5, lane = tid & 31;
    int wm = warp & 3, wn = warp >> 2;
    int lg = lane >> 2, lt = lane & 3;

    const float* x1b = d_x1 + (size_t)b * Cc * HW;
    uint32_t smem_u32 = (uint32_t)__cvta_generic_to_shared(dynsm);
    uint32_t ws_u32 = smem_u32 + PATCH_F * 4;

    for (int idx = tid; idx < PATCH_F + WS_F; idx += 256) dynsm[idx] = 0.f;
    __syncthreads();

    float acc[2][7][4];
#pragma unroll
    for (int mt = 0; mt < 2; mt++)
#pragma unroll
        for (int nt = 0; nt < 7; nt++)
#pragma unroll
            for (int e = 0; e < 4; e++) acc[mt][nt][e] = 0.f;

#define STAGE(CHUNK, BUF)                                                          \
    {                                                                              \
        int ci0_ = (CHUNK) * 8;                                                    \
        int kk0_ = ci0_ * 9;                                                       \
        for (int idx = tid; idx < 2528; idx += 256) {                              \
            if (idx < 512) {                                                       \
                int ciL = idx >> 6;                                                \
                int r = (idx >> 4) & 3;                                            \
                int j = idx & 15;                                                  \
                int gy = h0 - 1 + r;                                               \
                if ((unsigned)gy < (unsigned)Hh) {                                 \
                    const float* src =                                             \
                        x1b + (size_t)(ci0_ + ciL) * HW + gy * Ww + j * 4;         \
                    uint32_t dst = smem_u32 +                                      \
                        ((((BUF) * 8 + ciL) * 4 + r) * 72 + 4 + j * 4) * 4;        \
                    CP16(dst, src);                                                \
                }                                                                  \
            } else {                                                               \
                int t = idx - 512;                                                 \
                int col = t / 18;                                                  \
                int j = t - col * 18;                                              \
                int cog = n0 + col;                                                \
                if (cog < CO_ALL) {                                                \
                    const float* src =                                             \
                        (cog < CO_OFF ? offw + (size_t)cog * 2304                  \
                                      : maskw + (size_t)(cog - CO_OFF) * 2304) +   \
                        kk0_ + j * 4;                                              \
                    uint32_t dst =                                                 \
                        ws_u32 + (((BUF) * 112 + col) * 76 + j * 4) * 4;           \
                    CP16(dst, src);                                                \
                }                                                                  \
            }                                                                      \
        }                                                                          \
        CP_COMMIT();                                                               \
    }

    STAGE(0, 0);
    for (int c = 0; c < 32; c++) {
        int buf = c & 1;
        if (c < 31) {
            STAGE(c + 1, buf ^ 1);
        } else {
            CP_COMMIT();  // empty group keeps wait count uniform
        }
        CP_WAIT1();
        __syncthreads();

        const float* pb = patchp + (size_t)buf * 8 * 4 * 72;
        const float* wb = wsp + (size_t)buf * 112 * 76;
#pragma unroll
        for (int ks = 0; ks < 9; ks++) {
            int kb = ks * 8;
            int qa = kb + lt;
            int ciA = qa / 9; int ta = qa - ciA * 9;
            int kia = ta / 3; int kja = ta - kia * 3;
            int qb = qa + 4;
            int ciB = qb / 9; int tb = qb - ciB * 9;
            int kib = tb / 3; int kjb = tb - kib * 3;

            unsigned bfr[7][2];
#pragma unroll
            for (int nt = 0; nt < 7; nt++) {
                int n = wn * 56 + nt * 8 + lg;
                bfr[nt][0] = __float_as_uint(wb[n * 76 + kb + lt]);
                bfr[nt][1] = __float_as_uint(wb[n * 76 + kb + lt + 4]);
            }
#pragma unroll
            for (int mt = 0; mt < 2; mt++) {
                int rm = wm * 32 + mt * 16;
                int hL = rm >> 6;
                int w0 = (rm & 63) + lg;
                unsigned afr[4];
                afr[0] = __float_as_uint(pb[(ciA * 4 + hL + kia) * 72 + 3 + w0 + kja]);
                afr[1] = __float_as_uint(pb[(ciA * 4 + hL + kia) * 72 + 11 + w0 + kja]);
                afr[2] = __float_as_uint(pb[(ciB * 4 + hL + kib) * 72 + 3 + w0 + kjb]);
                afr[3] = __float_as_uint(pb[(ciB * 4 + hL + kib) * 72 + 11 + w0 + kjb]);
#pragma unroll
                for (int nt = 0; nt < 7; nt++) {
                    asm volatile(
                        "mma.sync.aligned.m16n8k8.row.col.f32.tf32.tf32.f32 "
                        "{%0,%1,%2,%3},{%4,%5,%6,%7},{%8,%9},{%0,%1,%2,%3};"
                        : "+f"(acc[mt][nt][0]), "+f"(acc[mt][nt][1]),
                          "+f"(acc[mt][nt][2]), "+f"(acc[mt][nt][3])
                        : "r"(afr[0]), "r"(afr[1]), "r"(afr[2]), "r"(afr[3]),
                          "r"(bfr[nt][0]), "r"(bfr[nt][1]));
                }
            }
        }
        __syncthreads();
    }
#undef STAGE

#pragma unroll
    for (int mt = 0; mt < 2; mt++) {
        int rm = wm * 32 + mt * 16;
#pragma unroll
        for (int nt = 0; nt < 7; nt++) {
            int ncol = wn * 56 + nt * 8 + lt * 2;
#pragma unroll
            for (int e = 0; e < 4; e++) {
                int co = n0 + ncol + (e & 1);
                int p = p0 + rm + lg + ((e >> 1) * 8);
                float v = acc[mt][nt][e];
                if (co < CO_OFF)
                    d_offb[((size_t)b * CO_OFF + co) * HW + p] = v + offbias[co];
                else if (co < CO_ALL)
                    d_maskb[((size_t)b * CO_MASK + (co - CO_OFF)) * HW + p] =
                        v + maskbias[co - CO_OFF];
            }
        }
    }
}

// ---------------- K6: softmax over consecutive flat groups of 9 -----------
// also resets d_stats for the next graph replay (zero-after-use invariant)
__global__ __launch_bounds__(256) void k_softmax() {
    __shared__ float sm[2304];
    int tid = threadIdx.x;
    if (blockIdx.x == 0 && tid < Bz * 2) d_stats[tid] = 0.0;
    size_t base = (size_t)blockIdx.x * 2304;
#pragma unroll
    for (int idx = tid; idx < 2304; idx += 256) sm[idx] = d_maskb[base + idx];
    __syncthreads();
    float* p = sm + tid * 9;
    float v[9];
    float mx = -1e30f;
#pragma unroll
    for (int i = 0; i < 9; i++) {
        v[i] = p[i];
        mx = fmaxf(mx, v[i]);
    }
    float s = 0.f;
#pragma unroll
    for (int i = 0; i < 9; i++) {
        v[i] = expf(v[i] - mx);
        s += v[i];
    }
    float inv = 1.f / s;
#pragma unroll
    for (int i = 0; i < 9; i++) p[i] = v[i] * inv;
    __syncthreads();
#pragma unroll
    for (int idx = tid; idx < 2304; idx += 256) d_maskb[base + idx] = sm[idx];
}

// ---------------- K7: deformable sampling + f32x2 output einsum -----------
#define WSM_F 9344
#define VS_F (8 * 4 * 288)
#define OUTB_F (32 * 129)
#define SAMPLE_SMEM ((WSM_F + VS_F + OUTB_F) * 4)  // 90752 bytes

__global__ __launch_bounds__(256) void k_sample(const float* __restrict__ outw,
                                                const float* __restrict__ outbias,
                                                float* __restrict__ out) {
    extern __shared__ float sm2[];
    float* wsm = sm2;
    float* vsbase = sm2 + WSM_F;
    float* outbf = sm2 + WSM_F + VS_F;

    int tid = threadIdx.x;
    int warp = tid >> 5, lane = tid & 31;
    int bg = blockIdx.x >> 5;
    int b = bg >> 3, g = bg & 7;
    int p0 = (blockIdx.x & 31) * 128;

    for (int idx = tid; idx < 32 * 288; idx += 256) {
        int o = idx / 288, k = idx - o * 288;
        wsm[o * 292 + k] = outw[(size_t)(g * OG + o) * 288 + k];
    }
    __syncthreads();

    const float* inpg = d_inp + (size_t)(b * Gg + g) * HW * CG;
    const float* offbase = d_offb + ((size_t)b * CO_OFF + g * 18) * HW;
    const float* mbase = d_maskb + ((size_t)b * CO_MASK + g * Nn) * HW;
    float* vsw = vsbase + warp * 4 * 288;
    const ulonglong2* wv2 = reinterpret_cast<const ulonglong2*>(&wsm[lane * 292]);

    int pbase = p0 + warp * 16;
#pragma unroll 1
    for (int pass = 0; pass < 4; pass++) {
#pragma unroll
        for (int i = 0; i < 4; i++) {
            int p = pbase + pass * 4 + i;
            int h = p >> 6, w = p & 63;
            const float* offp = offbase + p;
            const float* mp = mbase + p;
            float* vsd = vsw + i * 288;
#pragma unroll
            for (int n = 0; n < Nn; n++) {
                float dy = offp[(size_t)(n * 2) * HW];
                float dx = offp[(size_t)(n * 2 + 1) * HW];
                float m = mp[(size_t)n * HW];
                float py = dy + (float)(n / 3) + (float)(h - 1);
                float px = dx + (float)(n % 3) + (float)(w - 1);
                float fy = floorf(py), fx = floorf(px);
                int y0 = (int)fy, x0 = (int)fx;
                float wy = py - fy, wx = px - fx;
                float v = 0.f;
                {
                    int yi = y0, xi = x0;
                    if ((unsigned)yi < (unsigned)Hh && (unsigned)xi < (unsigned)Ww)
                        v += (1.f - wy) * (1.f - wx) *
                             inpg[(size_t)(yi * Ww + xi) * CG + lane];
                }
                {
                    int yi = y0, xi = x0 + 1;
                    if ((unsigned)yi < (unsigned)Hh && (unsigned)xi < (unsigned)Ww)
                        v += (1.f - wy) * wx *
                             inpg[(size_t)(yi * Ww + xi) * CG + lane];
                }
                {
                    int yi = y0 + 1, xi = x0;
                    if ((unsigned)yi < (unsigned)Hh && (unsigned)xi < (unsigned)Ww)
                        v += wy * (1.f - wx) *
                             inpg[(size_t)(yi * Ww + xi) * CG + lane];
                }
                {
                    int yi = y0 + 1, xi = x0 + 1;
                    if ((unsigned)yi < (unsigned)Hh && (unsigned)xi < (unsigned)Ww)
                        v += wy * wx * inpg[(size_t)(yi * Ww + xi) * CG + lane];
                }
                vsd[lane * 9 + n] = v * m;
            }
        }
        __syncwarp();

        // einsum: packed f32x2, even/odd k lanes, horizontal add at end
        const ulonglong2* v0 = reinterpret_cast<const ulonglong2*>(vsw);
        const ulonglong2* v1 = reinterpret_cast<const ulonglong2*>(vsw + 288);
        const ulonglong2* v2 = reinterpret_cast<const ulonglong2*>(vsw + 576);
        const ulonglong2* v3 = reinterpret_cast<const ulonglong2*>(vsw + 864);
        unsigned long long A0 = 0ull, A1 = 0ull, A2 = 0ull, A3 = 0ull;
#pragma unroll 8
        for (int k = 0; k < 72; k++) {
            ulonglong2 ww = wv2[k];
            ulonglong2 q;
            q = v0[k];
            FMA2(A0, q.x, ww.x);
            FMA2(A0, q.y, ww.y);
            q = v1[k];
            FMA2(A1, q.x, ww.x);
            FMA2(A1, q.y, ww.y);
            q = v2[k];
            FMA2(A2, q.x, ww.x);
            FMA2(A2, q.y, ww.y);
            q = v3[k];
            FMA2(A3, q.x, ww.x);
            FMA2(A3, q.y, ww.y);
        }
        float lo, hi, a0, a1, a2, a3;
        UNPK(lo, hi, A0); a0 = lo + hi;
        UNPK(lo, hi, A1); a1 = lo + hi;
        UNPK(lo, hi, A2); a2 = lo + hi;
        UNPK(lo, hi, A3); a3 = lo + hi;
        int colb = warp * 16 + pass * 4;
        outbf[lane * 129 + colb + 0] = a0;
        outbf[lane * 129 + colb + 1] = a1;
        outbf[lane * 129 + colb + 2] = a2;
        outbf[lane * 129 + colb + 3] = a3;
        __syncwarp();
    }
    __syncthreads();

    for (int idx = tid; idx < 4096; idx += 256) {
        int o = idx >> 7, pp = idx & 127;
        out[((size_t)b * Oo + g * OG + o) * HW + p0 + pp] =
            outbf[o * 129 + pp] + outbias[g * OG + o];
    }
}

// ---------------- launcher -------------------------------------------------
static cudaStream_t g_side_stream() {
    static cudaStream_t s = [] {
        cudaStream_t t;
        cudaStreamCreateWithFlags(&t, cudaStreamNonBlocking);
        return t;
    }();
    return s;
}
static cudaEvent_t g_ev_fork() {
    static cudaEvent_t e = [] {
        cudaEvent_t t;
        cudaEventCreateWithFlags(&t, cudaEventDisableTiming);
        return t;
    }();
    return e;
}
static cudaEvent_t g_ev_join() {
    static cudaEvent_t e = [] {
        cudaEvent_t t;
        cudaEventCreateWithFlags(&t, cudaEventDisableTiming);
        return t;
    }();
    return e;
}

extern "C" void kernel_launch(void* const* d_in, const int* in_sizes, int n_in,
                              void* d_out, int out_size) {
    const float* x = (const float*)d_in[0];
    const float* in_proj_w = (const float*)d_in[1];
    const float* in_proj_b = (const float*)d_in[2];
    const float* dw_w = (const float*)d_in[3];
    const float* dw_b = (const float*)d_in[4];
    const float* off_w = (const float*)d_in[5];
    const float* off_b = (const float*)d_in[6];
    const float* mask_w = (const float*)d_in[7];
    const float* mask_b = (const float*)d_in[8];
    const float* out_w = (const float*)d_in[9];
    const float* out_b = (const float*)d_in[10];
    float* out = (float*)d_out;

    cudaFuncSetAttribute(k_heads_mma, cudaFuncAttributeMaxDynamicSharedMemorySize,
                         HEADS_SMEM);
    cudaFuncSetAttribute(k_sample, cudaFuncAttributeMaxDynamicSharedMemorySize,
                         SAMPLE_SMEM);

    cudaStream_t s2 = g_side_stream();
    cudaEvent_t eF = g_ev_fork();
    cudaEvent_t eJ = g_ev_join();

    // ---- fork: inproj runs on a parallel branch (only k_sample needs d_inp)
    cudaEventRecord(eF, 0);
    cudaStreamWaitEvent(s2, eF, 0);
    {
        dim3 grid(HW / 64, Oo / 64, Bz);
        k_inproj<<<grid, 256, 0, s2>>>(x, in_proj_w, in_proj_b);
    }
    cudaEventRecord(eJ, s2);

    // ---- main branch: dwconv -> lngelu(inline stats) -> heads -> softmax
    k_dwconv<<<Bz * Cc, 256>>>(x, dw_w, dw_b);
    {
        int total4 = Bz * Cc * HW / 4;
        k_lngelu<<<(total4 + 255) / 256, 256>>>();
    }
    {
        dim3 grid(HW / 128, 2, Bz);
        k_heads_mma<<<grid, 256, HEADS_SMEM>>>(off_w, off_b, mask_w, mask_b);
    }
    k_softmax<<<512, 256>>>();  // also re-zeroes d_stats for next replay

    // ---- join: sample needs d_inp + d_offb + d_maskb
    cudaStreamWaitEvent(0, eJ, 0);
    k_sample<<<1024, 256, SAMPLE_SMEM>>>(out_w, out_b, out);
}

// round 12
// speedup vs baseline: 1.0806x; 1.0806x over previous
#include <cuda_runtime.h>
#include <math.h>
#include <stdint.h>

// Problem constants
#define Bz 4
#define Cc 256
#define Oo 256
#define Gg 8
#define CG 32      // C/G
#define OG 32      // O/G
#define Hh 64
#define Ww 64
#define HW 4096
#define Nn 9
#define CO_OFF 144
#define CO_MASK 72
#define CO_ALL 216

// ---------------- scratch (device globals; no allocation allowed) ----------
__device__ float d_inp[(size_t)Bz * Gg * HW * CG];   // 16 MB  layout [b][g][p][c]
__device__ float d_x1[(size_t)Bz * Cc * HW];          // 16 MB  layout [b][c][p]
__device__ float d_offb[(size_t)Bz * CO_OFF * HW];    // 9 MB   layout [b][co][p]
__device__ float d_maskb[(size_t)Bz * CO_MASK * HW];  // 4.5 MB layout [b][co][p]
__device__ double d_stats[Bz * 2];

#define CP16(dst, src) \
    asm volatile("cp.async.cg.shared.global [%0], [%1], 16;" ::"r"(dst), "l"(src) : "memory")
#define CP_COMMIT() asm volatile("cp.async.commit_group;" ::: "memory")
#define CP_WAIT1() asm volatile("cp.async.wait_group 1;" ::: "memory")

// ---------------- K1: in_proj (1x1 conv) -> d_inp [b][g][p][c] ------------
__global__ __launch_bounds__(256) void k_inproj(const float* __restrict__ x,
                                                const float* __restrict__ Wp,
                                                const float* __restrict__ bp) {
    int b = blockIdx.z;
    int d0 = blockIdx.y * 64;
    int p0 = blockIdx.x * 64;
    __shared__ float Xs[16][64];
    __shared__ float Ws[16][65];
    int tid = threadIdx.x;
    int tx = tid & 15, ty = tid >> 4;
    float acc[4][4];
#pragma unroll
    for (int j = 0; j < 4; j++)
#pragma unroll
        for (int i = 0; i < 4; i++) acc[j][i] = 0.f;
    const float* xb = x + (size_t)b * Cc * HW;
    for (int c0 = 0; c0 < Cc; c0 += 16) {
        for (int idx = tid; idx < 1024; idx += 256) {
            int k = idx >> 6, pp = idx & 63;
            Xs[k][pp] = xb[(size_t)(c0 + k) * HW + p0 + pp];
        }
        for (int idx = tid; idx < 1024; idx += 256) {
            int dd = idx >> 4, k = idx & 15;
            Ws[k][dd] = Wp[(size_t)(d0 + dd) * Cc + c0 + k];
        }
        __syncthreads();
#pragma unroll
        for (int k = 0; k < 16; k++) {
            float a[4], bb[4];
#pragma unroll
            for (int j = 0; j < 4; j++) a[j] = Xs[k][ty * 4 + j];
#pragma unroll
            for (int i = 0; i < 4; i++) bb[i] = Ws[k][tx * 4 + i];
#pragma unroll
            for (int j = 0; j < 4; j++)
#pragma unroll
                for (int i = 0; i < 4; i++) acc[j][i] += a[j] * bb[i];
        }
        __syncthreads();
    }
#pragma unroll
    for (int j = 0; j < 4; j++) {
        int p = p0 + ty * 4 + j;
#pragma unroll
        for (int i = 0; i < 4; i++) {
            int d = d0 + tx * 4 + i;
            d_inp[(((size_t)b * Gg + (d >> 5)) * HW + p) * CG + (d & 31)] =
                acc[j][i] + bp[d];
        }
    }
}

// ---------------- K2: depthwise 3x3 conv + partial LN sums ----------------
__global__ __launch_bounds__(256) void k_dwconv(const float* __restrict__ x,
                                                const float* __restrict__ dww,
                                                const float* __restrict__ dwb) {
    int bc = blockIdx.x;
    int b = bc >> 8, c = bc & 255;
    const float* xp = x + (size_t)(b * Cc + c) * HW;
    float* outp = d_x1 + (size_t)(b * Cc + c) * HW;
    float wr[9];
#pragma unroll
    for (int t = 0; t < 9; t++) wr[t] = dww[c * 9 + t];
    float bias = dwb[c];
    double s1 = 0.0, s2 = 0.0;
    int tid = threadIdx.x;
    for (int p = tid; p < HW; p += 256) {
        int h = p >> 6, w = p & 63;
        float acc = bias;
#pragma unroll
        for (int dy = 0; dy < 3; dy++) {
            int yy = h + dy - 1;
            if ((unsigned)yy < (unsigned)Hh) {
#pragma unroll
                for (int dx = 0; dx < 3; dx++) {
                    int xx = w + dx - 1;
                    if ((unsigned)xx < (unsigned)Ww)
                        acc += xp[yy * Ww + xx] * wr[dy * 3 + dx];
                }
            }
        }
        outp[p] = acc;
        s1 += (double)acc;
        s2 += (double)acc * (double)acc;
    }
    __shared__ double rs1[256];
    __shared__ double rs2[256];
    rs1[tid] = s1;
    rs2[tid] = s2;
    __syncthreads();
    for (int off = 128; off > 0; off >>= 1) {
        if (tid < off) {
            rs1[tid] += rs1[tid + off];
            rs2[tid] += rs2[tid + off];
        }
        __syncthreads();
    }
    if (tid == 0) {
        atomicAdd(&d_stats[b * 2 + 0], rs1[0]);
        atomicAdd(&d_stats[b * 2 + 1], rs2[0]);
    }
}

// ---------------- K4: LN (inline stats) + exact GELU, float4 --------------
__global__ __launch_bounds__(256) void k_lngelu() {
    __shared__ float s_mu, s_istd;
    size_t idx4 = (size_t)blockIdx.x * 256 + threadIdx.x;
    const size_t total4 = (size_t)Bz * Cc * HW / 4;
    int b = blockIdx.x >> 10;  // 1024 blocks per batch image
    if (threadIdx.x == 0) {
        const double Np = (double)Cc * HW;
        double mu = d_stats[b * 2 + 0] / Np;
        double var = d_stats[b * 2 + 1] / Np - mu * mu;
        s_mu = (float)mu;
        s_istd = (float)(1.0 / sqrt(var + 1e-5));
    }
    __syncthreads();
    if (idx4 >= total4) return;
    float mu = s_mu, istd = s_istd;
    float4 q = reinterpret_cast<float4*>(d_x1)[idx4];
    float v;
    v = (q.x - mu) * istd;
    q.x = 0.5f * v * (1.f + erff(v * 0.70710678118654752f));
    v = (q.y - mu) * istd;
    q.y = 0.5f * v * (1.f + erff(v * 0.70710678118654752f));
    v = (q.z - mu) * istd;
    q.z = 0.5f * v * (1.f + erff(v * 0.70710678118654752f));
    v = (q.w - mu) * istd;
    q.w = 0.5f * v * (1.f + erff(v * 0.70710678118654752f));
    reinterpret_cast<float4*>(d_x1)[idx4] = q;
}

// ---------------- K5: heads conv as implicit-GEMM tf32 mma.sync -----------
// (known-best 128-px config; measured 117us, tensor 47.6%)
#define PATCH_F (2 * 8 * 4 * 72)     // 4608 floats
#define WS_F (2 * 112 * 76)          // 17024 floats
#define HEADS_SMEM ((PATCH_F + WS_F) * 4)  // 86528 bytes

__global__ __launch_bounds__(256) void k_heads_mma(const float* __restrict__ offw,
                                                   const float* __restrict__ offbias,
                                                   const float* __restrict__ maskw,
                                                   const float* __restrict__ maskbias) {
    extern __shared__ float dynsm[];
    float* patchp = dynsm;                 // [(buf*8+ci)*4+r]*72 + col
    float* wsp = dynsm + PATCH_F;          // [(buf*112+col)*76 + k]

    int b = blockIdx.z;
    int p0 = blockIdx.x * 128;
    int n0 = blockIdx.y * 112;
    int h0 = p0 >> 6;
    int tid = threadIdx.x;
    int warp = tid >> 5, lane = tid & 31;
    int wm = warp & 3, wn = warp >> 2;
    int lg = lane >> 2, lt = lane & 3;

    const float* x1b = d_x1 + (size_t)b * Cc * HW;
    uint32_t smem_u32 = (uint32_t)__cvta_generic_to_shared(dynsm);
    uint32_t ws_u32 = smem_u32 + PATCH_F * 4;

    for (int idx = tid; idx < PATCH_F + WS_F; idx += 256) dynsm[idx] = 0.f;
    __syncthreads();

    float acc[2][7][4];
#pragma unroll
    for (int mt = 0; mt < 2; mt++)
#pragma unroll
        for (int nt = 0; nt < 7; nt++)
#pragma unroll
            for (int e = 0; e < 4; e++) acc[mt][nt][e] = 0.f;

#define STAGE(CHUNK, BUF)                                                          \
    {                                                                              \
        int ci0_ = (CHUNK) * 8;                                                    \
        int kk0_ = ci0_ * 9;                                                       \
        for (int idx = tid; idx < 2528; idx += 256) {                              \
            if (idx < 512) {                                                       \
                int ciL = idx >> 6;                                                \
                int r = (idx >> 4) & 3;                                            \
                int j = idx & 15;                                                  \
                int gy = h0 - 1 + r;                                               \
                if ((unsigned)gy < (unsigned)Hh) {                                 \
                    const float* src =                                             \
                        x1b + (size_t)(ci0_ + ciL) * HW + gy * Ww + j * 4;         \
                    uint32_t dst = smem_u32 +                                      \
                        ((((BUF) * 8 + ciL) * 4 + r) * 72 + 4 + j * 4) * 4;        \
                    CP16(dst, src);                                                \
                }                                                                  \
            } else {                                                               \
                int t = idx - 512;                                                 \
                int col = t / 18;                                                  \
                int j = t - col * 18;                                              \
                int cog = n0 + col;                                                \
                if (cog < CO_ALL) {                                                \
                    const float* src =                                             \
                        (cog < CO_OFF ? offw + (size_t)cog * 2304                  \
                                      : maskw + (size_t)(cog - CO_OFF) * 2304) +   \
                        kk0_ + j * 4;                                              \
                    uint32_t dst =                                                 \
                        ws_u32 + (((BUF) * 112 + col) * 76 + j * 4) * 4;           \
                    CP16(dst, src);                                                \
                }                                                                  \
            }                                                                      \
        }                                                                          \
        CP_COMMIT();                                                               \
    }

    STAGE(0, 0);
    for (int c = 0; c < 32; c++) {
        int buf = c & 1;
        if (c < 31) {
            STAGE(c + 1, buf ^ 1);
        } else {
            CP_COMMIT();  // empty group keeps wait count uniform
        }
        CP_WAIT1();
        __syncthreads();

        const float* pb = patchp + (size_t)buf * 8 * 4 * 72;
        const float* wb = wsp + (size_t)buf * 112 * 76;
#pragma unroll
        for (int ks = 0; ks < 9; ks++) {
            int kb = ks * 8;
            int qa = kb + lt;
            int ciA = qa / 9; int ta = qa - ciA * 9;
            int kia = ta / 3; int kja = ta - kia * 3;
            int qb = qa + 4;
            int ciB = qb / 9; int tb = qb - ciB * 9;
            int kib = tb / 3; int kjb = tb - kib * 3;

            unsigned bfr[7][2];
#pragma unroll
            for (int nt = 0; nt < 7; nt++) {
                int n = wn * 56 + nt * 8 + lg;
                bfr[nt][0] = __float_as_uint(wb[n * 76 + kb + lt]);
                bfr[nt][1] = __float_as_uint(wb[n * 76 + kb + lt + 4]);
            }
#pragma unroll
            for (int mt = 0; mt < 2; mt++) {
                int rm = wm * 32 + mt * 16;
                int hL = rm >> 6;
                int w0 = (rm & 63) + lg;
                unsigned afr[4];
                afr[0] = __float_as_uint(pb[(ciA * 4 + hL + kia) * 72 + 3 + w0 + kja]);
                afr[1] = __float_as_uint(pb[(ciA * 4 + hL + kia) * 72 + 11 + w0 + kja]);
                afr[2] = __float_as_uint(pb[(ciB * 4 + hL + kib) * 72 + 3 + w0 + kjb]);
                afr[3] = __float_as_uint(pb[(ciB * 4 + hL + kib) * 72 + 11 + w0 + kjb]);
#pragma unroll
                for (int nt = 0; nt < 7; nt++) {
                    asm volatile(
                        "mma.sync.aligned.m16n8k8.row.col.f32.tf32.tf32.f32 "
                        "{%0,%1,%2,%3},{%4,%5,%6,%7},{%8,%9},{%0,%1,%2,%3};"
                        : "+f"(acc[mt][nt][0]), "+f"(acc[mt][nt][1]),
                          "+f"(acc[mt][nt][2]), "+f"(acc[mt][nt][3])
                        : "r"(afr[0]), "r"(afr[1]), "r"(afr[2]), "r"(afr[3]),
                          "r"(bfr[nt][0]), "r"(bfr[nt][1]));
                }
            }
        }
        __syncthreads();
    }
#undef STAGE

#pragma unroll
    for (int mt = 0; mt < 2; mt++) {
        int rm = wm * 32 + mt * 16;
#pragma unroll
        for (int nt = 0; nt < 7; nt++) {
            int ncol = wn * 56 + nt * 8 + lt * 2;
#pragma unroll
            for (int e = 0; e < 4; e++) {
                int co = n0 + ncol + (e & 1);
                int p = p0 + rm + lg + ((e >> 1) * 8);
                float v = acc[mt][nt][e];
                if (co < CO_OFF)
                    d_offb[((size_t)b * CO_OFF + co) * HW + p] = v + offbias[co];
                else if (co < CO_ALL)
                    d_maskb[((size_t)b * CO_MASK + (co - CO_OFF)) * HW + p] =
                        v + maskbias[co - CO_OFF];
            }
        }
    }
}

// ---------------- K6: softmax over consecutive flat groups of 9 -----------
// also resets d_stats for the next graph replay (zero-after-use invariant)
__global__ __launch_bounds__(256) void k_softmax() {
    __shared__ float sm[2304];
    int tid = threadIdx.x;
    if (blockIdx.x == 0 && tid < Bz * 2) d_stats[tid] = 0.0;
    size_t base = (size_t)blockIdx.x * 2304;
#pragma unroll
    for (int idx = tid; idx < 2304; idx += 256) sm[idx] = d_maskb[base + idx];
    __syncthreads();
    float* p = sm + tid * 9;
    float v[9];
    float mx = -1e30f;
#pragma unroll
    for (int i = 0; i < 9; i++) {
        v[i] = p[i];
        mx = fmaxf(mx, v[i]);
    }
    float s = 0.f;
#pragma unroll
    for (int i = 0; i < 9; i++) {
        v[i] = expf(v[i] - mx);
        s += v[i];
    }
    float inv = 1.f / s;
#pragma unroll
    for (int i = 0; i < 9; i++) p[i] = v[i] * inv;
    __syncthreads();
#pragma unroll
    for (int idx = tid; idx < 2304; idx += 256) d_maskb[base + idx] = sm[idx];
}

// ---------------- K7: deformable sampling + output einsum (R6 proven) -----
#define WSM_F 9344
#define VS_F (8 * 4 * 288)
#define OUTB_F (32 * 129)
#define SAMPLE_SMEM ((WSM_F + VS_F + OUTB_F) * 4)  // 90752 bytes

__global__ __launch_bounds__(256) void k_sample(const float* __restrict__ outw,
                                                const float* __restrict__ outbias,
                                                float* __restrict__ out) {
    extern __shared__ float sm2[];
    float* wsm = sm2;
    float* vsbase = sm2 + WSM_F;
    float* outbf = sm2 + WSM_F + VS_F;

    int tid = threadIdx.x;
    int warp = tid >> 5, lane = tid & 31;
    int bg = blockIdx.x >> 5;
    int b = bg >> 3, g = bg & 7;
    int p0 = (blockIdx.x & 31) * 128;

    for (int idx = tid; idx < 32 * 288; idx += 256) {
        int o = idx / 288, k = idx - o * 288;
        wsm[o * 292 + k] = outw[(size_t)(g * OG + o) * 288 + k];
    }
    __syncthreads();

    const float* inpg = d_inp + (size_t)(b * Gg + g) * HW * CG;
    const float* offbase = d_offb + ((size_t)b * CO_OFF + g * 18) * HW;
    const float* mbase = d_maskb + ((size_t)b * CO_MASK + g * Nn) * HW;
    float* vsw = vsbase + warp * 4 * 288;
    const float4* wv = reinterpret_cast<const float4*>(&wsm[lane * 292]);

    int pbase = p0 + warp * 16;
#pragma unroll 1
    for (int pass = 0; pass < 4; pass++) {
#pragma unroll
        for (int i = 0; i < 4; i++) {
            int p = pbase + pass * 4 + i;
            int h = p >> 6, w = p & 63;
            const float* offp = offbase + p;
            const float* mp = mbase + p;
            float* vsd = vsw + i * 288;
#pragma unroll
            for (int n = 0; n < Nn; n++) {
                float dy = offp[(size_t)(n * 2) * HW];
                float dx = offp[(size_t)(n * 2 + 1) * HW];
                float m = mp[(size_t)n * HW];
                float py = dy + (float)(n / 3) + (float)(h - 1);
                float px = dx + (float)(n % 3) + (float)(w - 1);
                float fy = floorf(py), fx = floorf(px);
                int y0 = (int)fy, x0 = (int)fx;
                float wy = py - fy, wx = px - fx;
                float v = 0.f;
                {
                    int yi = y0, xi = x0;
                    if ((unsigned)yi < (unsigned)Hh && (unsigned)xi < (unsigned)Ww)
                        v += (1.f - wy) * (1.f - wx) *
                             inpg[(size_t)(yi * Ww + xi) * CG + lane];
                }
                {
                    int yi = y0, xi = x0 + 1;
                    if ((unsigned)yi < (unsigned)Hh && (unsigned)xi < (unsigned)Ww)
                        v += (1.f - wy) * wx *
                             inpg[(size_t)(yi * Ww + xi) * CG + lane];
                }
                {
                    int yi = y0 + 1, xi = x0;
                    if ((unsigned)yi < (unsigned)Hh && (unsigned)xi < (unsigned)Ww)
                        v += wy * (1.f - wx) *
                             inpg[(size_t)(yi * Ww + xi) * CG + lane];
                }
                {
                    int yi = y0 + 1, xi = x0 + 1;
                    if ((unsigned)yi < (unsigned)Hh && (unsigned)xi < (unsigned)Ww)
                        v += wy * wx * inpg[(size_t)(yi * Ww + xi) * CG + lane];
                }
                vsd[lane * 9 + n] = v * m;
            }
        }
        __syncwarp();

        const float4* v0 = reinterpret_cast<const float4*>(vsw);
        const float4* v1 = reinterpret_cast<const float4*>(vsw + 288);
        const float4* v2 = reinterpret_cast<const float4*>(vsw + 576);
        const float4* v3 = reinterpret_cast<const float4*>(vsw + 864);
        float a0 = 0.f, a1 = 0.f, a2 = 0.f, a3 = 0.f;
#pragma unroll 8
        for (int k = 0; k < 72; k++) {
            float4 ww = wv[k];
            float4 q;
            q = v0[k]; a0 += q.x * ww.x + q.y * ww.y + q.z * ww.z + q.w * ww.w;
            q = v1[k]; a1 += q.x * ww.x + q.y * ww.y + q.z * ww.z + q.w * ww.w;
            q = v2[k]; a2 += q.x * ww.x + q.y * ww.y + q.z * ww.z + q.w * ww.w;
            q = v3[k]; a3 += q.x * ww.x + q.y * ww.y + q.z * ww.z + q.w * ww.w;
        }
        int colb = warp * 16 + pass * 4;
        outbf[lane * 129 + colb + 0] = a0;
        outbf[lane * 129 + colb + 1] = a1;
        outbf[lane * 129 + colb + 2] = a2;
        outbf[lane * 129 + colb + 3] = a3;
        __syncwarp();
    }
    __syncthreads();

    for (int idx = tid; idx < 4096; idx += 256) {
        int o = idx >> 7, pp = idx & 127;
        out[((size_t)b * Oo + g * OG + o) * HW + p0 + pp] =
            outbf[o * 129 + pp] + outbias[g * OG + o];
    }
}

// ---------------- launcher -------------------------------------------------
static cudaStream_t g_side_stream() {
    static cudaStream_t s = [] {
        cudaStream_t t;
        cudaStreamCreateWithFlags(&t, cudaStreamNonBlocking);
        return t;
    }();
    return s;
}
static cudaEvent_t g_ev_fork() {
    static cudaEvent_t e = [] {
        cudaEvent_t t;
        cudaEventCreateWithFlags(&t, cudaEventDisableTiming);
        return t;
    }();
    return e;
}
static cudaEvent_t g_ev_join() {
    static cudaEvent_t e = [] {
        cudaEvent_t t;
        cudaEventCreateWithFlags(&t, cudaEventDisableTiming);
        return t;
    }();
    return e;
}

extern "C" void kernel_launch(void* const* d_in, const int* in_sizes, int n_in,
                              void* d_out, int out_size) {
    const float* x = (const float*)d_in[0];
    const float* in_proj_w = (const float*)d_in[1];
    const float* in_proj_b = (const float*)d_in[2];
    const float* dw_w = (const float*)d_in[3];
    const float* dw_b = (const float*)d_in[4];
    const float* off_w = (const float*)d_in[5];
    const float* off_b = (const float*)d_in[6];
    const float* mask_w = (const float*)d_in[7];
    const float* mask_b = (const float*)d_in[8];
    const float* out_w = (const float*)d_in[9];
    const float* out_b = (const float*)d_in[10];
    float* out = (float*)d_out;

    cudaFuncSetAttribute(k_heads_mma, cudaFuncAttributeMaxDynamicSharedMemorySize,
                         HEADS_SMEM);
    cudaFuncSetAttribute(k_sample, cudaFuncAttributeMaxDynamicSharedMemorySize,
                         SAMPLE_SMEM);

    cudaStream_t s2 = g_side_stream();
    cudaEvent_t eF = g_ev_fork();
    cudaEvent_t eJ = g_ev_join();

    // ---- fork: inproj runs on a parallel branch (only k_sample needs d_inp)
    cudaEventRecord(eF, 0);
    cudaStreamWaitEvent(s2, eF, 0);
    {
        dim3 grid(HW / 64, Oo / 64, Bz);
        k_inproj<<<grid, 256, 0, s2>>>(x, in_proj_w, in_proj_b);
    }
    cudaEventRecord(eJ, s2);

    // ---- main branch: dwconv -> lngelu(inline stats) -> heads -> softmax
    k_dwconv<<<Bz * Cc, 256>>>(x, dw_w, dw_b);
    {
        int total4 = Bz * Cc * HW / 4;
        k_lngelu<<<(total4 + 255) / 256, 256>>>();
    }
    {
        dim3 grid(HW / 128, 2, Bz);
        k_heads_mma<<<grid, 256, HEADS_SMEM>>>(off_w, off_b, mask_w, mask_b);
    }
    k_softmax<<<512, 256>>>();  // also re-zeroes d_stats for next replay

    // ---- join: sample needs d_inp + d_offb + d_maskb
    cudaStreamWaitEvent(0, eJ, 0);
    k_sample<<<1024, 256, SAMPLE_SMEM>>>(out_w, out_b, out);
}

// round 13
// speedup vs baseline: 1.1473x; 1.0618x over previous
#include <cuda_runtime.h>
#include <math.h>
#include <stdint.h>

// Problem constants
#define Bz 4
#define Cc 256
#define Oo 256
#define Gg 8
#define CG 32      // C/G
#define OG 32      // O/G
#define Hh 64
#define Ww 64
#define HW 4096
#define Nn 9
#define CO_OFF 144
#define CO_MASK 72
#define CO_ALL 216

// ---------------- scratch (device globals; no allocation allowed) ----------
__device__ float d_inp[(size_t)Bz * Gg * HW * CG];   // 16 MB  layout [b][g][p][c]
__device__ float d_x1[(size_t)Bz * Cc * HW];          // 16 MB  layout [b][c][p]
__device__ float d_offb[(size_t)Bz * CO_OFF * HW];    // 9 MB   layout [b][co][p]
__device__ float d_maskb[(size_t)Bz * CO_MASK * HW];  // 4.5 MB layout [b][co][p]
__device__ double d_stats[Bz * 2];

#define CP16(dst, src) \
    asm volatile("cp.async.cg.shared.global [%0], [%1], 16;" ::"r"(dst), "l"(src) : "memory")
#define CP_COMMIT() asm volatile("cp.async.commit_group;" ::: "memory")
#define CP_WAIT1() asm volatile("cp.async.wait_group 1;" ::: "memory")

// ---------------- K1: in_proj (1x1 conv) -> d_inp [b][g][p][c] ------------
__global__ __launch_bounds__(256) void k_inproj(const float* __restrict__ x,
                                                const float* __restrict__ Wp,
                                                const float* __restrict__ bp) {
    int b = blockIdx.z;
    int d0 = blockIdx.y * 64;
    int p0 = blockIdx.x * 64;
    __shared__ float Xs[16][64];
    __shared__ float Ws[16][65];
    int tid = threadIdx.x;
    int tx = tid & 15, ty = tid >> 4;
    float acc[4][4];
#pragma unroll
    for (int j = 0; j < 4; j++)
#pragma unroll
        for (int i = 0; i < 4; i++) acc[j][i] = 0.f;
    const float* xb = x + (size_t)b * Cc * HW;
    for (int c0 = 0; c0 < Cc; c0 += 16) {
        for (int idx = tid; idx < 1024; idx += 256) {
            int k = idx >> 6, pp = idx & 63;
            Xs[k][pp] = xb[(size_t)(c0 + k) * HW + p0 + pp];
        }
        for (int idx = tid; idx < 1024; idx += 256) {
            int dd = idx >> 4, k = idx & 15;
            Ws[k][dd] = Wp[(size_t)(d0 + dd) * Cc + c0 + k];
        }
        __syncthreads();
#pragma unroll
        for (int k = 0; k < 16; k++) {
            float a[4], bb[4];
#pragma unroll
            for (int j = 0; j < 4; j++) a[j] = Xs[k][ty * 4 + j];
#pragma unroll
            for (int i = 0; i < 4; i++) bb[i] = Ws[k][tx * 4 + i];
#pragma unroll
            for (int j = 0; j < 4; j++)
#pragma unroll
                for (int i = 0; i < 4; i++) acc[j][i] += a[j] * bb[i];
        }
        __syncthreads();
    }
#pragma unroll
    for (int j = 0; j < 4; j++) {
        int p = p0 + ty * 4 + j;
#pragma unroll
        for (int i = 0; i < 4; i++) {
            int d = d0 + tx * 4 + i;
            d_inp[(((size_t)b * Gg + (d >> 5)) * HW + p) * CG + (d & 31)] =
                acc[j][i] + bp[d];
        }
    }
}

// ---------------- K2: depthwise 3x3 conv + partial LN sums ----------------
__global__ __launch_bounds__(256) void k_dwconv(const float* __restrict__ x,
                                                const float* __restrict__ dww,
                                                const float* __restrict__ dwb) {
    int bc = blockIdx.x;
    int b = bc >> 8, c = bc & 255;
    const float* xp = x + (size_t)(b * Cc + c) * HW;
    float* outp = d_x1 + (size_t)(b * Cc + c) * HW;
    float wr[9];
#pragma unroll
    for (int t = 0; t < 9; t++) wr[t] = dww[c * 9 + t];
    float bias = dwb[c];
    double s1 = 0.0, s2 = 0.0;
    int tid = threadIdx.x;
    for (int p = tid; p < HW; p += 256) {
        int h = p >> 6, w = p & 63;
        float acc = bias;
#pragma unroll
        for (int dy = 0; dy < 3; dy++) {
            int yy = h + dy - 1;
            if ((unsigned)yy < (unsigned)Hh) {
#pragma unroll
                for (int dx = 0; dx < 3; dx++) {
                    int xx = w + dx - 1;
                    if ((unsigned)xx < (unsigned)Ww)
                        acc += xp[yy * Ww + xx] * wr[dy * 3 + dx];
                }
            }
        }
        outp[p] = acc;
        s1 += (double)acc;
        s2 += (double)acc * (double)acc;
    }
    __shared__ double rs1[256];
    __shared__ double rs2[256];
    rs1[tid] = s1;
    rs2[tid] = s2;
    __syncthreads();
    for (int off = 128; off > 0; off >>= 1) {
        if (tid < off) {
            rs1[tid] += rs1[tid + off];
            rs2[tid] += rs2[tid + off];
        }
        __syncthreads();
    }
    if (tid == 0) {
        atomicAdd(&d_stats[b * 2 + 0], rs1[0]);
        atomicAdd(&d_stats[b * 2 + 1], rs2[0]);
    }
}

// ---------------- K4: LN (inline stats) + exact GELU, float4 --------------
__global__ __launch_bounds__(256) void k_lngelu() {
    __shared__ float s_mu, s_istd;
    size_t idx4 = (size_t)blockIdx.x * 256 + threadIdx.x;
    const size_t total4 = (size_t)Bz * Cc * HW / 4;
    int b = blockIdx.x >> 10;  // 1024 blocks per batch image
    if (threadIdx.x == 0) {
        const double Np = (double)Cc * HW;
        double mu = d_stats[b * 2 + 0] / Np;
        double var = d_stats[b * 2 + 1] / Np - mu * mu;
        s_mu = (float)mu;
        s_istd = (float)(1.0 / sqrt(var + 1e-5));
    }
    __syncthreads();
    if (idx4 >= total4) return;
    float mu = s_mu, istd = s_istd;
    float4 q = reinterpret_cast<float4*>(d_x1)[idx4];
    float v;
    v = (q.x - mu) * istd;
    q.x = 0.5f * v * (1.f + erff(v * 0.70710678118654752f));
    v = (q.y - mu) * istd;
    q.y = 0.5f * v * (1.f + erff(v * 0.70710678118654752f));
    v = (q.z - mu) * istd;
    q.z = 0.5f * v * (1.f + erff(v * 0.70710678118654752f));
    v = (q.w - mu) * istd;
    q.w = 0.5f * v * (1.f + erff(v * 0.70710678118654752f));
    reinterpret_cast<float4*>(d_x1)[idx4] = q;
}

// ---------------- K5: heads conv as implicit-GEMM tf32 mma.sync -----------
// (known-best 128-px config; measured ~116us, tensor 47%)
#define PATCH_F (2 * 8 * 4 * 72)     // 4608 floats
#define WS_F (2 * 112 * 76)          // 17024 floats
#define HEADS_SMEM ((PATCH_F + WS_F) * 4)  // 86528 bytes

__global__ __launch_bounds__(256) void k_heads_mma(const float* __restrict__ offw,
                                                   const float* __restrict__ offbias,
                                                   const float* __restrict__ maskw,
                                                   const float* __restrict__ maskbias) {
    extern __shared__ float dynsm[];
    float* patchp = dynsm;                 // [(buf*8+ci)*4+r]*72 + col
    float* wsp = dynsm + PATCH_F;          // [(buf*112+col)*76 + k]

    int b = blockIdx.z;
    int p0 = blockIdx.x * 128;
    int n0 = blockIdx.y * 112;
    int h0 = p0 >> 6;
    int tid = threadIdx.x;
    int warp = tid >> 5, lane = tid & 31;
    int wm = warp & 3, wn = warp >> 2;
    int lg = lane >> 2, lt = lane & 3;

    const float* x1b = d_x1 + (size_t)b * Cc * HW;
    uint32_t smem_u32 = (uint32_t)__cvta_generic_to_shared(dynsm);
    uint32_t ws_u32 = smem_u32 + PATCH_F * 4;

    for (int idx = tid; idx < PATCH_F + WS_F; idx += 256) dynsm[idx] = 0.f;
    __syncthreads();

    float acc[2][7][4];
#pragma unroll
    for (int mt = 0; mt < 2; mt++)
#pragma unroll
        for (int nt = 0; nt < 7; nt++)
#pragma unroll
            for (int e = 0; e < 4; e++) acc[mt][nt][e] = 0.f;

#define STAGE(CHUNK, BUF)                                                          \
    {                                                                              \
        int ci0_ = (CHUNK) * 8;                                                    \
        int kk0_ = ci0_ * 9;                                                       \
        for (int idx = tid; idx < 2528; idx += 256) {                              \
            if (idx < 512) {                                                       \
                int ciL = idx >> 6;                                                \
                int r = (idx >> 4) & 3;                                            \
                int j = idx & 15;                                                  \
                int gy = h0 - 1 + r;                                               \
                if ((unsigned)gy < (unsigned)Hh) {                                 \
                    const float* src =                                             \
                        x1b + (size_t)(ci0_ + ciL) * HW + gy * Ww + j * 4;         \
                    uint32_t dst = smem_u32 +                                      \
                        ((((BUF) * 8 + ciL) * 4 + r) * 72 + 4 + j * 4) * 4;        \
                    CP16(dst, src);                                                \
                }                                                                  \
            } else {                                                               \
                int t = idx - 512;                                                 \
                int col = t / 18;                                                  \
                int j = t - col * 18;                                              \
                int cog = n0 + col;                                                \
                if (cog < CO_ALL) {                                                \
                    const float* src =                                             \
                        (cog < CO_OFF ? offw + (size_t)cog * 2304                  \
                                      : maskw + (size_t)(cog - CO_OFF) * 2304) +   \
                        kk0_ + j * 4;                                              \
                    uint32_t dst =                                                 \
                        ws_u32 + (((BUF) * 112 + col) * 76 + j * 4) * 4;           \
                    CP16(dst, src);                                                \
                }                                                                  \
            }                                                                      \
        }                                                                          \
        CP_COMMIT();                                                               \
    }

    STAGE(0, 0);
    for (int c = 0; c < 32; c++) {
        int buf = c & 1;
        if (c < 31) {
            STAGE(c + 1, buf ^ 1);
        } else {
            CP_COMMIT();  // empty group keeps wait count uniform
        }
        CP_WAIT1();
        __syncthreads();

        const float* pb = patchp + (size_t)buf * 8 * 4 * 72;
        const float* wb = wsp + (size_t)buf * 112 * 76;
#pragma unroll
        for (int ks = 0; ks < 9; ks++) {
            int kb = ks * 8;
            int qa = kb + lt;
            int ciA = qa / 9; int ta = qa - ciA * 9;
            int kia = ta / 3; int kja = ta - kia * 3;
            int qb = qa + 4;
            int ciB = qb / 9; int tb = qb - ciB * 9;
            int kib = tb / 3; int kjb = tb - kib * 3;

            unsigned bfr[7][2];
#pragma unroll
            for (int nt = 0; nt < 7; nt++) {
                int n = wn * 56 + nt * 8 + lg;
                bfr[nt][0] = __float_as_uint(wb[n * 76 + kb + lt]);
                bfr[nt][1] = __float_as_uint(wb[n * 76 + kb + lt + 4]);
            }
#pragma unroll
            for (int mt = 0; mt < 2; mt++) {
                int rm = wm * 32 + mt * 16;
                int hL = rm >> 6;
                int w0 = (rm & 63) + lg;
                unsigned afr[4];
                afr[0] = __float_as_uint(pb[(ciA * 4 + hL + kia) * 72 + 3 + w0 + kja]);
                afr[1] = __float_as_uint(pb[(ciA * 4 + hL + kia) * 72 + 11 + w0 + kja]);
                afr[2] = __float_as_uint(pb[(ciB * 4 + hL + kib) * 72 + 3 + w0 + kjb]);
                afr[3] = __float_as_uint(pb[(ciB * 4 + hL + kib) * 72 + 11 + w0 + kjb]);
#pragma unroll
                for (int nt = 0; nt < 7; nt++) {
                    asm volatile(
                        "mma.sync.aligned.m16n8k8.row.col.f32.tf32.tf32.f32 "
                        "{%0,%1,%2,%3},{%4,%5,%6,%7},{%8,%9},{%0,%1,%2,%3};"
                        : "+f"(acc[mt][nt][0]), "+f"(acc[mt][nt][1]),
                          "+f"(acc[mt][nt][2]), "+f"(acc[mt][nt][3])
                        : "r"(afr[0]), "r"(afr[1]), "r"(afr[2]), "r"(afr[3]),
                          "r"(bfr[nt][0]), "r"(bfr[nt][1]));
                }
            }
        }
        __syncthreads();
    }
#undef STAGE

#pragma unroll
    for (int mt = 0; mt < 2; mt++) {
        int rm = wm * 32 + mt * 16;
#pragma unroll
        for (int nt = 0; nt < 7; nt++) {
            int ncol = wn * 56 + nt * 8 + lt * 2;
#pragma unroll
            for (int e = 0; e < 4; e++) {
                int co = n0 + ncol + (e & 1);
                int p = p0 + rm + lg + ((e >> 1) * 8);
                float v = acc[mt][nt][e];
                if (co < CO_OFF)
                    d_offb[((size_t)b * CO_OFF + co) * HW + p] = v + offbias[co];
                else if (co < CO_ALL)
                    d_maskb[((size_t)b * CO_MASK + (co - CO_OFF)) * HW + p] =
                        v + maskbias[co - CO_OFF];
            }
        }
    }
}

// ---------------- K6: softmax over consecutive flat groups of 9 -----------
// also resets d_stats for the next graph replay (zero-after-use invariant)
__global__ __launch_bounds__(256) void k_softmax() {
    __shared__ float sm[2304];
    int tid = threadIdx.x;
    if (blockIdx.x == 0 && tid < Bz * 2) d_stats[tid] = 0.0;
    size_t base = (size_t)blockIdx.x * 2304;
#pragma unroll
    for (int idx = tid; idx < 2304; idx += 256) sm[idx] = d_maskb[base + idx];
    __syncthreads();
    float* p = sm + tid * 9;
    float v[9];
    float mx = -1e30f;
#pragma unroll
    for (int i = 0; i < 9; i++) {
        v[i] = p[i];
        mx = fmaxf(mx, v[i]);
    }
    float s = 0.f;
#pragma unroll
    for (int i = 0; i < 9; i++) {
        v[i] = expf(v[i] - mx);
        s += v[i];
    }
    float inv = 1.f / s;
#pragma unroll
    for (int i = 0; i < 9; i++) p[i] = v[i] * inv;
    __syncthreads();
#pragma unroll
    for (int idx = tid; idx < 2304; idx += 256) d_maskb[base + idx] = sm[idx];
}

// ---------------- K7: deformable sampling + output einsum -----------------
// Two-phase gather: phase 1 computes per-(pixel,tap) bilinear weights (mask &
// validity folded in, clamped indices) ONCE per warp (lane = pair) into smem;
// phase 2 does pure coalesced loads + FFMA. Einsum unchanged (proven float4).
#define WSM_F 9344
#define VS_F (8 * 4 * 288)
#define OUTB_F (32 * 129)
#define WQ_F (8 * 36 * 8)  // 2304 floats: per-warp [36 pairs][4 wgt + 4 idx]
#define SAMPLE_SMEM ((WSM_F + VS_F + OUTB_F + WQ_F) * 4)  // 99968 bytes

__global__ __launch_bounds__(256) void k_sample(const float* __restrict__ outw,
                                                const float* __restrict__ outbias,
                                                float* __restrict__ out) {
    extern __shared__ float sm2[];
    float* wsm = sm2;
    float* vsbase = sm2 + WSM_F;
    float* outbf = sm2 + WSM_F + VS_F;
    float* wqbase = sm2 + WSM_F + VS_F + OUTB_F;

    int tid = threadIdx.x;
    int warp = tid >> 5, lane = tid & 31;
    int bg = blockIdx.x >> 5;
    int b = bg >> 3, g = bg & 7;
    int p0 = (blockIdx.x & 31) * 128;

    for (int idx = tid; idx < 32 * 288; idx += 256) {
        int o = idx / 288, k = idx - o * 288;
        wsm[o * 292 + k] = outw[(size_t)(g * OG + o) * 288 + k];
    }
    __syncthreads();

    const float* inpg = d_inp + (size_t)(b * Gg + g) * HW * CG;
    const float* offbase = d_offb + ((size_t)b * CO_OFF + g * 18) * HW;
    const float* mbase = d_maskb + ((size_t)b * CO_MASK + g * Nn) * HW;
    float* vsw = vsbase + warp * 4 * 288;
    float* wq = wqbase + warp * 36 * 8;
    const float4* wv = reinterpret_cast<const float4*>(&wsm[lane * 292]);

    int pbase = p0 + warp * 16;
#pragma unroll 1
    for (int pass = 0; pass < 4; pass++) {
        // ---- phase 1: per-pair weights+indices (lane = pair, no redundancy)
#pragma unroll
        for (int rep = 0; rep < 2; rep++) {
            int q = lane + rep * 32;
            if (q < 36) {
                int i = q / 9, n = q - i * 9;
                int p = pbase + pass * 4 + i;
                int h = p >> 6, w = p & 63;
                float dy = offbase[(size_t)(n * 2) * HW + p];
                float dx = offbase[(size_t)(n * 2 + 1) * HW + p];
                float m = mbase[(size_t)n * HW + p];
                float py = dy + (float)(n / 3) + (float)(h - 1);
                float px = dx + (float)(n % 3) + (float)(w - 1);
                float fy = floorf(py), fx = floorf(px);
                int y0 = (int)fy, x0 = (int)fx;
                float wy = py - fy, wx = px - fx;
                bool vy0 = ((unsigned)y0 < (unsigned)Hh);
                bool vy1 = ((unsigned)(y0 + 1) < (unsigned)Hh);
                bool vx0 = ((unsigned)x0 < (unsigned)Ww);
                bool vx1 = ((unsigned)(x0 + 1) < (unsigned)Ww);
                int yc0 = min(max(y0, 0), Hh - 1);
                int yc1 = min(max(y0 + 1, 0), Hh - 1);
                int xc0 = min(max(x0, 0), Ww - 1);
                int xc1 = min(max(x0 + 1, 0), Ww - 1);
                float4 wgt;
                wgt.x = (vy0 && vx0) ? (1.f - wy) * (1.f - wx) * m : 0.f;
                wgt.y = (vy0 && vx1) ? (1.f - wy) * wx * m : 0.f;
                wgt.z = (vy1 && vx0) ? wy * (1.f - wx) * m : 0.f;
                wgt.w = (vy1 && vx1) ? wy * wx * m : 0.f;
                int4 iv;
                iv.x = (yc0 * Ww + xc0) * CG;
                iv.y = (yc0 * Ww + xc1) * CG;
                iv.z = (yc1 * Ww + xc0) * CG;
                iv.w = (yc1 * Ww + xc1) * CG;
                *reinterpret_cast<float4*>(&wq[q * 8]) = wgt;
                *reinterpret_cast<int4*>(&wq[q * 8 + 4]) = iv;
            }
        }
        __syncwarp();

        // ---- phase 2: pure gather (broadcast LDS + coalesced LDG + FFMA)
        {
            const float* ing = inpg + lane;
#pragma unroll 4
            for (int q = 0; q < 36; q++) {
                float4 wgt = *reinterpret_cast<const float4*>(&wq[q * 8]);
                int4 iv = *reinterpret_cast<const int4*>(&wq[q * 8 + 4]);
                float g00 = ing[iv.x];
                float g01 = ing[iv.y];
                float g10 = ing[iv.z];
                float g11 = ing[iv.w];
                float v = wgt.x * g00 + wgt.y * g01 + wgt.z * g10 + wgt.w * g11;
                vsw[(q / 9) * 288 + lane * 9 + (q % 9)] = v;
            }
        }
        __syncwarp();

        // ---- einsum: 4 pixels share each weight load (proven float4 path)
        const float4* v0 = reinterpret_cast<const float4*>(vsw);
        const float4* v1 = reinterpret_cast<const float4*>(vsw + 288);
        const float4* v2 = reinterpret_cast<const float4*>(vsw + 576);
        const float4* v3 = reinterpret_cast<const float4*>(vsw + 864);
        float a0 = 0.f, a1 = 0.f, a2 = 0.f, a3 = 0.f;
#pragma unroll 8
        for (int k = 0; k < 72; k++) {
            float4 ww = wv[k];
            float4 q;
            q = v0[k]; a0 += q.x * ww.x + q.y * ww.y + q.z * ww.z + q.w * ww.w;
            q = v1[k]; a1 += q.x * ww.x + q.y * ww.y + q.z * ww.z + q.w * ww.w;
            q = v2[k]; a2 += q.x * ww.x + q.y * ww.y + q.z * ww.z + q.w * ww.w;
            q = v3[k]; a3 += q.x * ww.x + q.y * ww.y + q.z * ww.z + q.w * ww.w;
        }
        int colb = warp * 16 + pass * 4;
        outbf[lane * 129 + colb + 0] = a0;
        outbf[lane * 129 + colb + 1] = a1;
        outbf[lane * 129 + colb + 2] = a2;
        outbf[lane * 129 + colb + 3] = a3;
        __syncwarp();
    }
    __syncthreads();

    for (int idx = tid; idx < 4096; idx += 256) {
        int o = idx >> 7, pp = idx & 127;
        out[((size_t)b * Oo + g * OG + o) * HW + p0 + pp] =
            outbf[o * 129 + pp] + outbias[g * OG + o];
    }
}

// ---------------- launcher -------------------------------------------------
static cudaStream_t g_side_stream() {
    static cudaStream_t s = [] {
        cudaStream_t t;
        cudaStreamCreateWithFlags(&t, cudaStreamNonBlocking);
        return t;
    }();
    return s;
}
static cudaEvent_t g_ev_fork() {
    static cudaEvent_t e = [] {
        cudaEvent_t t;
        cudaEventCreateWithFlags(&t, cudaEventDisableTiming);
        return t;
    }();
    return e;
}
static cudaEvent_t g_ev_join() {
    static cudaEvent_t e = [] {
        cudaEvent_t t;
        cudaEventCreateWithFlags(&t, cudaEventDisableTiming);
        return t;
    }();
    return e;
}

extern "C" void kernel_launch(void* const* d_in, const int* in_sizes, int n_in,
                              void* d_out, int out_size) {
    const float* x = (const float*)d_in[0];
    const float* in_proj_w = (const float*)d_in[1];
    const float* in_proj_b = (const float*)d_in[2];
    const float* dw_w = (const float*)d_in[3];
    const float* dw_b = (const float*)d_in[4];
    const float* off_w = (const float*)d_in[5];
    const float* off_b = (const float*)d_in[6];
    const float* mask_w = (const float*)d_in[7];
    const float* mask_b = (const float*)d_in[8];
    const float* out_w = (const float*)d_in[9];
    const float* out_b = (const float*)d_in[10];
    float* out = (float*)d_out;

    cudaFuncSetAttribute(k_heads_mma, cudaFuncAttributeMaxDynamicSharedMemorySize,
                         HEADS_SMEM);
    cudaFuncSetAttribute(k_sample, cudaFuncAttributeMaxDynamicSharedMemorySize,
                         SAMPLE_SMEM);

    cudaStream_t s2 = g_side_stream();
    cudaEvent_t eF = g_ev_fork();
    cudaEvent_t eJ = g_ev_join();

    // ---- fork: inproj runs on a parallel branch (only k_sample needs d_inp)
    cudaEventRecord(eF, 0);
    cudaStreamWaitEvent(s2, eF, 0);
    {
        dim3 grid(HW / 64, Oo / 64, Bz);
        k_inproj<<<grid, 256, 0, s2>>>(x, in_proj_w, in_proj_b);
    }
    cudaEventRecord(eJ, s2);

    // ---- main branch: dwconv -> lngelu(inline stats) -> heads -> softmax
    k_dwconv<<<Bz * Cc, 256>>>(x, dw_w, dw_b);
    {
        int total4 = Bz * Cc * HW / 4;
        k_lngelu<<<(total4 + 255) / 256, 256>>>();
    }
    {
        dim3 grid(HW / 128, 2, Bz);
        k_heads_mma<<<grid, 256, HEADS_SMEM>>>(off_w, off_b, mask_w, mask_b);
    }
    k_softmax<<<512, 256>>>();  // also re-zeroes d_stats for next replay

    // ---- join: sample needs d_inp + d_offb + d_maskb
    cudaStreamWaitEvent(0, eJ, 0);
    k_sample<<<1024, 256, SAMPLE_SMEM>>>(out_w, out_b, out);
}

// round 16
// speedup vs baseline: 1.1553x; 1.0070x over previous
#include <cuda_runtime.h>
#include <math.h>
#include <stdint.h>

// Problem constants
#define Bz 4
#define Cc 256
#define Oo 256
#define Gg 8
#define CG 32      // C/G
#define OG 32      // O/G
#define Hh 64
#define Ww 64
#define HW 4096
#define Nn 9
#define CO_OFF 144
#define CO_MASK 72
#define CO_ALL 216

// ---------------- scratch (device globals; no allocation allowed) ----------
__device__ float d_inp[(size_t)Bz * Gg * HW * CG];   // 16 MB  layout [b][g][p][c]
__device__ float d_x1[(size_t)Bz * Cc * HW];          // 16 MB  layout [b][c][p]
__device__ float d_offb[(size_t)Bz * CO_OFF * HW];    // 9 MB   layout [b][co][p]
__device__ float d_maskb[(size_t)Bz * CO_MASK * HW];  // 4.5 MB layout [b][co][p]
__device__ double d_stats[Bz * 2];

#define CP16(dst, src) \
    asm volatile("cp.async.cg.shared.global [%0], [%1], 16;" ::"r"(dst), "l"(src) : "memory")
#define CP_COMMIT() asm volatile("cp.async.commit_group;" ::: "memory")
#define CP_WAIT1() asm volatile("cp.async.wait_group 1;" ::: "memory")

// ---------------- K1: in_proj (1x1 conv) -> d_inp [b][g][p][c] ------------
__global__ __launch_bounds__(256) void k_inproj(const float* __restrict__ x,
                                                const float* __restrict__ Wp,
                                                const float* __restrict__ bp) {
    int b = blockIdx.z;
    int d0 = blockIdx.y * 64;
    int p0 = blockIdx.x * 64;
    __shared__ float Xs[16][64];
    __shared__ float Ws[16][65];
    int tid = threadIdx.x;
    int tx = tid & 15, ty = tid >> 4;
    float acc[4][4];
#pragma unroll
    for (int j = 0; j < 4; j++)
#pragma unroll
        for (int i = 0; i < 4; i++) acc[j][i] = 0.f;
    const float* xb = x + (size_t)b * Cc * HW;
    for (int c0 = 0; c0 < Cc; c0 += 16) {
        for (int idx = tid; idx < 1024; idx += 256) {
            int k = idx >> 6, pp = idx & 63;
            Xs[k][pp] = xb[(size_t)(c0 + k) * HW + p0 + pp];
        }
        for (int idx = tid; idx < 1024; idx += 256) {
            int dd = idx >> 4, k = idx & 15;
            Ws[k][dd] = Wp[(size_t)(d0 + dd) * Cc + c0 + k];
        }
        __syncthreads();
#pragma unroll
        for (int k = 0; k < 16; k++) {
            float a[4], bb[4];
#pragma unroll
            for (int j = 0; j < 4; j++) a[j] = Xs[k][ty * 4 + j];
#pragma unroll
            for (int i = 0; i < 4; i++) bb[i] = Ws[k][tx * 4 + i];
#pragma unroll
            for (int j = 0; j < 4; j++)
#pragma unroll
                for (int i = 0; i < 4; i++) acc[j][i] += a[j] * bb[i];
        }
        __syncthreads();
    }
#pragma unroll
    for (int j = 0; j < 4; j++) {
        int p = p0 + ty * 4 + j;
#pragma unroll
        for (int i = 0; i < 4; i++) {
            int d = d0 + tx * 4 + i;
            d_inp[(((size_t)b * Gg + (d >> 5)) * HW + p) * CG + (d & 31)] =
                acc[j][i] + bp[d];
        }
    }
}

// ---------------- K2: depthwise 3x3 conv + partial LN sums ----------------
__global__ __launch_bounds__(256) void k_dwconv(const float* __restrict__ x,
                                                const float* __restrict__ dww,
                                                const float* __restrict__ dwb) {
    int bc = blockIdx.x;
    int b = bc >> 8, c = bc & 255;
    const float* xp = x + (size_t)(b * Cc + c) * HW;
    float* outp = d_x1 + (size_t)(b * Cc + c) * HW;
    float wr[9];
#pragma unroll
    for (int t = 0; t < 9; t++) wr[t] = dww[c * 9 + t];
    float bias = dwb[c];
    double s1 = 0.0, s2 = 0.0;
    int tid = threadIdx.x;
    for (int p = tid; p < HW; p += 256) {
        int h = p >> 6, w = p & 63;
        float acc = bias;
#pragma unroll
        for (int dy = 0; dy < 3; dy++) {
            int yy = h + dy - 1;
            if ((unsigned)yy < (unsigned)Hh) {
#pragma unroll
                for (int dx = 0; dx < 3; dx++) {
                    int xx = w + dx - 1;
                    if ((unsigned)xx < (unsigned)Ww)
                        acc += xp[yy * Ww + xx] * wr[dy * 3 + dx];
                }
            }
        }
        outp[p] = acc;
        s1 += (double)acc;
        s2 += (double)acc * (double)acc;
    }
    __shared__ double rs1[256];
    __shared__ double rs2[256];
    rs1[tid] = s1;
    rs2[tid] = s2;
    __syncthreads();
    for (int off = 128; off > 0; off >>= 1) {
        if (tid < off) {
            rs1[tid] += rs1[tid + off];
            rs2[tid] += rs2[tid + off];
        }
        __syncthreads();
    }
    if (tid == 0) {
        atomicAdd(&d_stats[b * 2 + 0], rs1[0]);
        atomicAdd(&d_stats[b * 2 + 1], rs2[0]);
    }
}

// ---------------- K4: LN (inline stats) + exact GELU, float4 --------------
__global__ __launch_bounds__(256) void k_lngelu() {
    __shared__ float s_mu, s_istd;
    size_t idx4 = (size_t)blockIdx.x * 256 + threadIdx.x;
    const size_t total4 = (size_t)Bz * Cc * HW / 4;
    int b = blockIdx.x >> 10;  // 1024 blocks per batch image
    if (threadIdx.x == 0) {
        const double Np = (double)Cc * HW;
        double mu = d_stats[b * 2 + 0] / Np;
        double var = d_stats[b * 2 + 1] / Np - mu * mu;
        s_mu = (float)mu;
        s_istd = (float)(1.0 / sqrt(var + 1e-5));
    }
    __syncthreads();
    if (idx4 >= total4) return;
    float mu = s_mu, istd = s_istd;
    float4 q = reinterpret_cast<float4*>(d_x1)[idx4];
    float v;
    v = (q.x - mu) * istd;
    q.x = 0.5f * v * (1.f + erff(v * 0.70710678118654752f));
    v = (q.y - mu) * istd;
    q.y = 0.5f * v * (1.f + erff(v * 0.70710678118654752f));
    v = (q.z - mu) * istd;
    q.z = 0.5f * v * (1.f + erff(v * 0.70710678118654752f));
    v = (q.w - mu) * istd;
    q.w = 0.5f * v * (1.f + erff(v * 0.70710678118654752f));
    reinterpret_cast<float4*>(d_x1)[idx4] = q;
}

// ---------------- K5: heads conv as implicit-GEMM tf32 mma.sync -----------
// (known-best 128-px config; measured ~116us, tensor 47%)
#define PATCH_F (2 * 8 * 4 * 72)     // 4608 floats
#define WS_F (2 * 112 * 76)          // 17024 floats
#define HEADS_SMEM ((PATCH_F + WS_F) * 4)  // 86528 bytes

__global__ __launch_bounds__(256) void k_heads_mma(const float* __restrict__ offw,
                                                   const float* __restrict__ offbias,
                                                   const float* __restrict__ maskw,
                                                   const float* __restrict__ maskbias) {
    extern __shared__ float dynsm[];
    float* patchp = dynsm;                 // [(buf*8+ci)*4+r]*72 + col
    float* wsp = dynsm + PATCH_F;          // [(buf*112+col)*76 + k]

    int b = blockIdx.z;
    int p0 = blockIdx.x * 128;
    int n0 = blockIdx.y * 112;
    int h0 = p0 >> 6;
    int tid = threadIdx.x;
    int warp = tid >> 5, lane = tid & 31;
    int wm = warp & 3, wn = warp >> 2;
    int lg = lane >> 2, lt = lane & 3;

    const float* x1b = d_x1 + (size_t)b * Cc * HW;
    uint32_t smem_u32 = (uint32_t)__cvta_generic_to_shared(dynsm);
    uint32_t ws_u32 = smem_u32 + PATCH_F * 4;

    for (int idx = tid; idx < PATCH_F + WS_F; idx += 256) dynsm[idx] = 0.f;
    __syncthreads();

    float acc[2][7][4];
#pragma unroll
    for (int mt = 0; mt < 2; mt++)
#pragma unroll
        for (int nt = 0; nt < 7; nt++)
#pragma unroll
            for (int e = 0; e < 4; e++) acc[mt][nt][e] = 0.f;

#define STAGE(CHUNK, BUF)                                                          \
    {                                                                              \
        int ci0_ = (CHUNK) * 8;                                                    \
        int kk0_ = ci0_ * 9;                                                       \
        for (int idx = tid; idx < 2528; idx += 256) {                              \
            if (idx < 512) {                                                       \
                int ciL = idx >> 6;                                                \
                int r = (idx >> 4) & 3;                                            \
                int j = idx & 15;                                                  \
                int gy = h0 - 1 + r;                                               \
                if ((unsigned)gy < (unsigned)Hh) {                                 \
                    const float* src =                                             \
                        x1b + (size_t)(ci0_ + ciL) * HW + gy * Ww + j * 4;         \
                    uint32_t dst = smem_u32 +                                      \
                        ((((BUF) * 8 + ciL) * 4 + r) * 72 + 4 + j * 4) * 4;        \
                    CP16(dst, src);                                                \
                }                                                                  \
            } else {                                                               \
                int t = idx - 512;                                                 \
                int col = t / 18;                                                  \
                int j = t - col * 18;                                              \
                int cog = n0 + col;                                                \
                if (cog < CO_ALL) {                                                \
                    const float* src =                                             \
                        (cog < CO_OFF ? offw + (size_t)cog * 2304                  \
                                      : maskw + (size_t)(cog - CO_OFF) * 2304) +   \
                        kk0_ + j * 4;                                              \
                    uint32_t dst =                                                 \
                        ws_u32 + (((BUF) * 112 + col) * 76 + j * 4) * 4;           \
                    CP16(dst, src);                                                \
                }                                                                  \
            }                                                                      \
        }                                                                          \
        CP_COMMIT();                                                               \
    }

    STAGE(0, 0);
    for (int c = 0; c < 32; c++) {
        int buf = c & 1;
        if (c < 31) {
            STAGE(c + 1, buf ^ 1);
        } else {
            CP_COMMIT();  // empty group keeps wait count uniform
        }
        CP_WAIT1();
        __syncthreads();

        const float* pb = patchp + (size_t)buf * 8 * 4 * 72;
        const float* wb = wsp + (size_t)buf * 112 * 76;
#pragma unroll
        for (int ks = 0; ks < 9; ks++) {
            int kb = ks * 8;
            int qa = kb + lt;
            int ciA = qa / 9; int ta = qa - ciA * 9;
            int kia = ta / 3; int kja = ta - kia * 3;
            int qb = qa + 4;
            int ciB = qb / 9; int tb = qb - ciB * 9;
            int kib = tb / 3; int kjb = tb - kib * 3;

            unsigned bfr[7][2];
#pragma unroll
            for (int nt = 0; nt < 7; nt++) {
                int n = wn * 56 + nt * 8 + lg;
                bfr[nt][0] = __float_as_uint(wb[n * 76 + kb + lt]);
                bfr[nt][1] = __float_as_uint(wb[n * 76 + kb + lt + 4]);
            }
#pragma unroll
            for (int mt = 0; mt < 2; mt++) {
                int rm = wm * 32 + mt * 16;
                int hL = rm >> 6;
                int w0 = (rm & 63) + lg;
                unsigned afr[4];
                afr[0] = __float_as_uint(pb[(ciA * 4 + hL + kia) * 72 + 3 + w0 + kja]);
                afr[1] = __float_as_uint(pb[(ciA * 4 + hL + kia) * 72 + 11 + w0 + kja]);
                afr[2] = __float_as_uint(pb[(ciB * 4 + hL + kib) * 72 + 3 + w0 + kjb]);
                afr[3] = __float_as_uint(pb[(ciB * 4 + hL + kib) * 72 + 11 + w0 + kjb]);
#pragma unroll
                for (int nt = 0; nt < 7; nt++) {
                    asm volatile(
                        "mma.sync.aligned.m16n8k8.row.col.f32.tf32.tf32.f32 "
                        "{%0,%1,%2,%3},{%4,%5,%6,%7},{%8,%9},{%0,%1,%2,%3};"
                        : "+f"(acc[mt][nt][0]), "+f"(acc[mt][nt][1]),
                          "+f"(acc[mt][nt][2]), "+f"(acc[mt][nt][3])
                        : "r"(afr[0]), "r"(afr[1]), "r"(afr[2]), "r"(afr[3]),
                          "r"(bfr[nt][0]), "r"(bfr[nt][1]));
                }
            }
        }
        __syncthreads();
    }
#undef STAGE

#pragma unroll
    for (int mt = 0; mt < 2; mt++) {
        int rm = wm * 32 + mt * 16;
#pragma unroll
        for (int nt = 0; nt < 7; nt++) {
            int ncol = wn * 56 + nt * 8 + lt * 2;
#pragma unroll
            for (int e = 0; e < 4; e++) {
                int co = n0 + ncol + (e & 1);
                int p = p0 + rm + lg + ((e >> 1) * 8);
                float v = acc[mt][nt][e];
                if (co < CO_OFF)
                    d_offb[((size_t)b * CO_OFF + co) * HW + p] = v + offbias[co];
                else if (co < CO_ALL)
                    d_maskb[((size_t)b * CO_MASK + (co - CO_OFF)) * HW + p] =
                        v + maskbias[co - CO_OFF];
            }
        }
    }
}

// ---------------- K6: softmax over consecutive flat groups of 9 -----------
// also resets d_stats for the next graph replay (zero-after-use invariant)
__global__ __launch_bounds__(256) void k_softmax() {
    __shared__ float sm[2304];
    int tid = threadIdx.x;
    if (blockIdx.x == 0 && tid < Bz * 2) d_stats[tid] = 0.0;
    size_t base = (size_t)blockIdx.x * 2304;
#pragma unroll
    for (int idx = tid; idx < 2304; idx += 256) sm[idx] = d_maskb[base + idx];
    __syncthreads();
    float* p = sm + tid * 9;
    float v[9];
    float mx = -1e30f;
#pragma unroll
    for (int i = 0; i < 9; i++) {
        v[i] = p[i];
        mx = fmaxf(mx, v[i]);
    }
    float s = 0.f;
#pragma unroll
    for (int i = 0; i < 9; i++) {
        v[i] = expf(v[i] - mx);
        s += v[i];
    }
    float inv = 1.f / s;
#pragma unroll
    for (int i = 0; i < 9; i++) p[i] = v[i] * inv;
    __syncthreads();
#pragma unroll
    for (int idx = tid; idx < 2304; idx += 256) d_maskb[base + idx] = sm[idx];
}

// ---------------- K7: deformable sampling + output einsum -----------------
// 64 pixels/block (2048 blocks), 2-px einsum passes, direct float2 stores.
// smem 60.4KB -> 3 blocks/SM = 24 warps (+50% latency hiding on the gather).
#define WSM_F 9344               // 32 x 292
#define VS2_F (8 * 2 * 288)      // 4608
#define WQ2_F (8 * 18 * 8)       // 1152
#define SAMPLE_SMEM ((WSM_F + VS2_F + WQ2_F) * 4)  // 60416 bytes

__global__ __launch_bounds__(256) void k_sample(const float* __restrict__ outw,
                                                const float* __restrict__ outbias,
                                                float* __restrict__ out) {
    extern __shared__ float sm2[];
    float* wsm = sm2;                          // [32][292]
    float* vsbase = sm2 + WSM_F;               // [8 warps][2 px][288]
    float* wqbase = sm2 + WSM_F + VS2_F;       // [8 warps][18 pairs][8]

    int tid = threadIdx.x;
    int warp = tid >> 5, lane = tid & 31;
    int bg = blockIdx.x >> 6;
    int b = bg >> 3, g = bg & 7;
    int p0 = (blockIdx.x & 63) * 64;

    for (int idx = tid; idx < 32 * 288; idx += 256) {
        int o = idx / 288, k = idx - o * 288;
        wsm[o * 292 + k] = outw[(size_t)(g * OG + o) * 288 + k];
    }
    __syncthreads();

    const float* inpg = d_inp + (size_t)(b * Gg + g) * HW * CG;
    const float* offbase = d_offb + ((size_t)b * CO_OFF + g * 18) * HW;
    const float* mbase = d_maskb + ((size_t)b * CO_MASK + g * Nn) * HW;
    float* vsw = vsbase + warp * 2 * 288;
    float* wq = wqbase + warp * 18 * 8;
    const float4* wv = reinterpret_cast<const float4*>(&wsm[lane * 292]);
    float bias = outbias[g * OG + lane];

    int pbase = p0 + warp * 8;
#pragma unroll 1
    for (int pass = 0; pass < 4; pass++) {
        int pp0 = pbase + pass * 2;
        // ---- phase 1: per-pair weights+indices (lane = pair, no redundancy)
        if (lane < 18) {
            int q = lane;
            int i = q / 9, n = q - i * 9;
            int p = pp0 + i;
            int h = p >> 6, w = p & 63;
            float dy = offbase[(size_t)(n * 2) * HW + p];
            float dx = offbase[(size_t)(n * 2 + 1) * HW + p];
            float m = mbase[(size_t)n * HW + p];
            float py = dy + (float)(n / 3) + (float)(h - 1);
            float px = dx + (float)(n % 3) + (float)(w - 1);
            float fy = floorf(py), fx = floorf(px);
            int y0 = (int)fy, x0 = (int)fx;
            float wy = py - fy, wx = px - fx;
            bool vy0 = ((unsigned)y0 < (unsigned)Hh);
            bool vy1 = ((unsigned)(y0 + 1) < (unsigned)Hh);
            bool vx0 = ((unsigned)x0 < (unsigned)Ww);
            bool vx1 = ((unsigned)(x0 + 1) < (unsigned)Ww);
            int yc0 = min(max(y0, 0), Hh - 1);
            int yc1 = min(max(y0 + 1, 0), Hh - 1);
            int xc0 = min(max(x0, 0), Ww - 1);
            int xc1 = min(max(x0 + 1, 0), Ww - 1);
            float4 wgt;
            wgt.x = (vy0 && vx0) ? (1.f - wy) * (1.f - wx) * m : 0.f;
            wgt.y = (vy0 && vx1) ? (1.f - wy) * wx * m : 0.f;
            wgt.z = (vy1 && vx0) ? wy * (1.f - wx) * m : 0.f;
            wgt.w = (vy1 && vx1) ? wy * wx * m : 0.f;
            int4 iv;
            iv.x = (yc0 * Ww + xc0) * CG;
            iv.y = (yc0 * Ww + xc1) * CG;
            iv.z = (yc1 * Ww + xc0) * CG;
            iv.w = (yc1 * Ww + xc1) * CG;
            *reinterpret_cast<float4*>(&wq[q * 8]) = wgt;
            *reinterpret_cast<int4*>(&wq[q * 8 + 4]) = iv;
        }
        __syncwarp();

        // ---- phase 2: pure gather (broadcast LDS + coalesced LDG + FFMA)
        {
            const float* ing = inpg + lane;
#pragma unroll 6
            for (int q = 0; q < 18; q++) {
                float4 wgt = *reinterpret_cast<const float4*>(&wq[q * 8]);
                int4 iv = *reinterpret_cast<const int4*>(&wq[q * 8 + 4]);
                float g00 = ing[iv.x];
                float g01 = ing[iv.y];
                float g10 = ing[iv.z];
                float g11 = ing[iv.w];
                float v = wgt.x * g00 + wgt.y * g01 + wgt.z * g10 + wgt.w * g11;
                vsw[(q / 9) * 288 + lane * 9 + (q % 9)] = v;
            }
        }
        __syncwarp();

        // ---- einsum: 2 pixels per weight load (k ascending, order unchanged)
        const float4* v0 = reinterpret_cast<const float4*>(vsw);
        const float4* v1 = reinterpret_cast<const float4*>(vsw + 288);
        float a0 = 0.f, a1 = 0.f;
#pragma unroll 8
        for (int k = 0; k < 72; k++) {
            float4 ww = wv[k];
            float4 q;
            q = v0[k]; a0 += q.x * ww.x + q.y * ww.y + q.z * ww.z + q.w * ww.w;
            q = v1[k]; a1 += q.x * ww.x + q.y * ww.y + q.z * ww.z + q.w * ww.w;
        }
        // direct store: lane = o, 2 contiguous pixels -> aligned float2
        float2 r;
        r.x = a0 + bias;
        r.y = a1 + bias;
        *reinterpret_cast<float2*>(
            &out[((size_t)b * Oo + g * OG + lane) * HW + pp0]) = r;
        __syncwarp();
    }
}

// ---------------- launcher -------------------------------------------------
static cudaStream_t g_side_stream() {
    static cudaStream_t s = [] {
        cudaStream_t t;
        cudaStreamCreateWithFlags(&t, cudaStreamNonBlocking);
        return t;
    }();
    return s;
}
static cudaEvent_t g_ev_fork() {
    static cudaEvent_t e = [] {
        cudaEvent_t t;
        cudaEventCreateWithFlags(&t, cudaEventDisableTiming);
        return t;
    }();
    return e;
}
static cudaEvent_t g_ev_join() {
    static cudaEvent_t e = [] {
        cudaEvent_t t;
        cudaEventCreateWithFlags(&t, cudaEventDisableTiming);
        return t;
    }();
    return e;
}

extern "C" void kernel_launch(void* const* d_in, const int* in_sizes, int n_in,
                              void* d_out, int out_size) {
    const float* x = (const float*)d_in[0];
    const float* in_proj_w = (const float*)d_in[1];
    const float* in_proj_b = (const float*)d_in[2];
    const float* dw_w = (const float*)d_in[3];
    const float* dw_b = (const float*)d_in[4];
    const float* off_w = (const float*)d_in[5];
    const float* off_b = (const float*)d_in[6];
    const float* mask_w = (const float*)d_in[7];
    const float* mask_b = (const float*)d_in[8];
    const float* out_w = (const float*)d_in[9];
    const float* out_b = (const float*)d_in[10];
    float* out = (float*)d_out;

    cudaFuncSetAttribute(k_heads_mma, cudaFuncAttributeMaxDynamicSharedMemorySize,
                         HEADS_SMEM);
    cudaFuncSetAttribute(k_sample, cudaFuncAttributeMaxDynamicSharedMemorySize,
                         SAMPLE_SMEM);

    cudaStream_t s2 = g_side_stream();
    cudaEvent_t eF = g_ev_fork();
    cudaEvent_t eJ = g_ev_join();

    // ---- fork: inproj runs on a parallel branch (only k_sample needs d_inp)
    cudaEventRecord(eF, 0);
    cudaStreamWaitEvent(s2, eF, 0);
    {
        dim3 grid(HW / 64, Oo / 64, Bz);
        k_inproj<<<grid, 256, 0, s2>>>(x, in_proj_w, in_proj_b);
    }
    cudaEventRecord(eJ, s2);

    // ---- main branch: dwconv -> lngelu(inline stats) -> heads -> softmax
    k_dwconv<<<Bz * Cc, 256>>>(x, dw_w, dw_b);
    {
        int total4 = Bz * Cc * HW / 4;
        k_lngelu<<<(total4 + 255) / 256, 256>>>();
    }
    {
        dim3 grid(HW / 128, 2, Bz);
        k_heads_mma<<<grid, 256, HEADS_SMEM>>>(off_w, off_b, mask_w, mask_b);
    }
    k_softmax<<<512, 256>>>();  // also re-zeroes d_stats for next replay

    // ---- join: sample needs d_inp + d_offb + d_maskb
    cudaStreamWaitEvent(0, eJ, 0);
    k_sample<<<2048, 256, SAMPLE_SMEM>>>(out_w, out_b, out);
}